// round 4
// baseline (speedup 1.0000x reference)
#include <cuda_runtime.h>
#include <cstddef>

#define NBLK   148
#define NTHR   1024
#define NWARPS (NBLK * 32)       // 4736
#define NPAIRS 65536             // 131072 rows / 2
#define MDIM   450

// Scratch (device globals; no allocation)
__device__ __align__(16) float g_Fpart[128 * 128];
__device__ __align__(16) float g_feat[452];
__device__ __align__(16) float g_h[452];
__device__ __align__(16) float g_feat2[452];
__device__ __align__(16) float g_h2[452];

// Grid barrier (monotonic generation -> graph-replay safe)
__device__ unsigned g_count = 0;
__device__ volatile unsigned g_gen = 0;

__device__ __forceinline__ void grid_bar()
{
    __syncthreads();
    if (threadIdx.x == 0) {
        const unsigned gen = g_gen;
        __threadfence();
        if (atomicAdd(&g_count, 1u) == (unsigned)gridDim.x - 1u) {
            atomicExch(&g_count, 0u);
            __threadfence();
            g_gen = gen + 1u;
        } else {
            while (g_gen == gen) { }
            __threadfence();
        }
    }
    __syncthreads();
}

// L2 prefetch helper: each calling thread touches nlines lines, strided.
__device__ __forceinline__ void l2_pf(const float* base, size_t line0,
                                      size_t my, size_t nthreads, int nlines)
{
    const char* p = (const char*)base;
    #pragma unroll
    for (int k = 0; k < 16; ++k) {
        if (k >= nlines) break;
        size_t line = line0 + my + (size_t)k * nthreads;
        asm volatile("prefetch.global.L2 [%0];" :: "l"(p + line * 128));
    }
}

// Warp-per-row 450x450 matvec: vout = [relu](W @ vin + b). Blocks 0..14.
__device__ __forceinline__ void mv450_stage(const float* __restrict__ W,
                                            const float* __restrict__ b,
                                            const float* __restrict__ vin_g,
                                            float* __restrict__ vout_g,
                                            bool do_relu, float* sh)
{
    const int tid = threadIdx.x;
    if (tid < MDIM) sh[tid] = __ldcg(vin_g + tid);
    __syncthreads();

    const int wid  = tid >> 5;
    const int lane = tid & 31;
    const int row  = blockIdx.x * 32 + wid;
    if (row < MDIM) {
        const float2* wr = reinterpret_cast<const float2*>(W + (size_t)row * MDIM);
        const float2* sv = reinterpret_cast<const float2*>(sh);
        float acc = 0.f;
        #pragma unroll
        for (int j = 0; j < 7; ++j) {
            const float2 w = __ldg(wr + lane + 32 * j);
            const float2 v = sv[lane + 32 * j];
            acc += w.x * v.x + w.y * v.y;
        }
        if (lane == 0) {
            const float2 w = __ldg(wr + 224);
            const float2 v = sv[224];
            acc += w.x * v.x + w.y * v.y;
        }
        #pragma unroll
        for (int o = 16; o; o >>= 1) acc += __shfl_xor_sync(0xFFFFFFFFu, acc, o);
        if (lane == 0) {
            float r = acc + __ldg(b + row);
            vout_g[row] = do_relu ? fmaxf(r, 0.f) : r;
        }
    }
}

__global__ void __launch_bounds__(NTHR, 1)
fused_kernel(const float* __restrict__ x,   const float* __restrict__ TwE,
             const float* __restrict__ PE,  const float* __restrict__ CE,
             const float* __restrict__ mE,
             const float* __restrict__ eW1, const float* __restrict__ eb1,
             const float* __restrict__ eW2, const float* __restrict__ eb2,
             const float* __restrict__ dW1, const float* __restrict__ db1,
             const float* __restrict__ dW2, const float* __restrict__ db2,
             float* __restrict__ out, int xoff)
{
    __shared__ float sh[10240];            // 40KB, reused per stage
    const int tid  = threadIdx.x;
    const int wid  = tid >> 5;
    const int lane = tid & 31;
    const int blk  = blockIdx.x;

    // ===== Stage 1: f partials. 128 blocks x 8 tp-rows each. =====
    // Warp = (row-pair, c-chunk): pr = wid&3 (rows 2pr,2pr+1), ch = wid>>2 (16 c's).
    if (blk < 128) {
        float* sx = sh;                    // [8][128] x rows
        float* sp = sh + 1024;             // [8 chunks][8 rows][128 i]
        sx[tid] = x[xoff + blk * 1024 + tid];
        __syncthreads();

        const int pr = wid & 3;
        const int ch = wid >> 2;
        const int i0 = lane * 4;
        const int r0 = pr * 2, r1 = r0 + 1;
        float4 a0 = {0,0,0,0}, a1 = {0,0,0,0};
        const int cb = ch * 16;
        #pragma unroll
        for (int cc = 0; cc < 16; ++cc) {
            const int c = cb + cc;
            const float4 ce = *reinterpret_cast<const float4*>(CE + c * 128 + i0);
            const float x0 = sx[r0 * 128 + c];
            const float x1 = sx[r1 * 128 + c];
            a0.x += x0 * ce.x; a0.y += x0 * ce.y; a0.z += x0 * ce.z; a0.w += x0 * ce.w;
            a1.x += x1 * ce.x; a1.y += x1 * ce.y; a1.z += x1 * ce.z; a1.w += x1 * ce.w;
        }
        *reinterpret_cast<float4*>(sp + (ch * 8 + r0) * 128 + i0) = a0;
        *reinterpret_cast<float4*>(sp + (ch * 8 + r1) * 128 + i0) = a1;
        __syncthreads();

        const int row = tid >> 7;          // 0..7
        const int i   = tid & 127;
        float s = 0.f;
        #pragma unroll
        for (int c2 = 0; c2 < 8; ++c2) s += sp[(c2 * 8 + row) * 128 + i];
        const int gr = blk * 8 + row;      // tp index
        const int t  = gr >> 8;
        const int p  = gr & 255;
        s *= __ldg(PE + p * 128 + i) * __ldg(TwE + t * 128 + i);
        __syncthreads();
        sh[tid] = s;                       // [row][i]
        __syncthreads();
        if (tid < 128) {
            float t2 = 0.f;
            #pragma unroll
            for (int r = 0; r < 8; ++r) t2 += sh[r * 128 + tid];
            g_Fpart[blk * 128 + tid] = t2;
        }
    } else {
        // Prefetch phase 0: dec_W2 lines [0, 20480*12) = 31.4MB
        l2_pf(dW2, 0, (size_t)(blk - 128) * NTHR + tid, 20480u * 32, 12);
    }
    grid_bar();

    // ===== Stage 2: feat = mE @ f (blocks 0..14) =====
    if (blk < 15) {
        if (tid < 128) {
            float s = 0.f;
            #pragma unroll 8
            for (int b = 0; b < 128; ++b) s += __ldcg(&g_Fpart[b * 128 + tid]);
            sh[tid] = s;
        }
        __syncthreads();
        const int row = blk * 32 + wid;
        if (row < MDIM) {
            const float* r = mE + row * 128;
            float acc = __ldg(r + lane)       * sh[lane]
                      + __ldg(r + lane + 32)  * sh[lane + 32]
                      + __ldg(r + lane + 64)  * sh[lane + 64]
                      + __ldg(r + lane + 96)  * sh[lane + 96];
            #pragma unroll
            for (int o = 16; o; o >>= 1) acc += __shfl_xor_sync(0xFFFFFFFFu, acc, o);
            if (lane == 0) g_feat[row] = acc;
        }
    } else {
        // Prefetch phase 1: next ~34.8MB
        l2_pf(dW2, 245760, (size_t)(blk - 15) * NTHR + tid, 136192u, 2);
    }
    grid_bar();

    // ===== Stages 3..5: 450x450 chain (blocks 0..14) =====
    if (blk < 15) mv450_stage(eW1, eb1, g_feat, g_h, true, sh);
    else l2_pf(dW2, 518144, (size_t)(blk - 15) * NTHR + tid, 136192u, 2); // ~+34.8MB
    grid_bar();
    if (blk < 15) mv450_stage(eW2, eb2, g_h, g_feat2, false, sh);
    grid_bar();
    if (blk < 15) mv450_stage(dW1, db1, g_feat2, g_h2, true, sh);
    grid_bar();

    // ===== Stage 6: out = dec_W2 @ h2 + db2 (131072 x 450) =====
    // Warp processes a row-pair as one contiguous 3600B segment:
    // 225 float4 per pair; lane j reads float4 idx lane+32k (k=0..6), lane0 reads 224.
    // v duplicated in smem: svv = h2 || h2 (900 floats) -> float4-aligned gathers.
    {
        for (int i = tid; i < 900; i += NTHR)
            sh[i] = __ldcg(&g_h2[(i < 450) ? i : (i - 450)]);
        __syncthreads();
        const float4* VV = reinterpret_cast<const float4*>(sh);
        const int gw = blk * 32 + wid;

        for (int pr = gw; pr < NPAIRS; pr += NWARPS) {
            const float4* wr = reinterpret_cast<const float4*>(dW2 + (size_t)pr * 900);
            float4 w0 = __ldcs(wr + lane);
            float4 w1 = __ldcs(wr + lane + 32);
            float4 w2 = __ldcs(wr + lane + 64);
            float4 w3 = __ldcs(wr + lane + 96);
            float4 w4 = __ldcs(wr + lane + 128);
            float4 w5 = __ldcs(wr + lane + 160);
            float4 w6 = __ldcs(wr + lane + 192);
            float4 wt;
            if (lane == 0) wt = __ldcs(wr + 224);

            float acc0 = 0.f, acc1 = 0.f;
            {   // k=0..2 : pure row0 (elements < 448)
                float4 v = VV[lane];
                acc0 += w0.x*v.x + w0.y*v.y + w0.z*v.z + w0.w*v.w;
                v = VV[lane + 32];
                acc0 += w1.x*v.x + w1.y*v.y + w1.z*v.z + w1.w*v.w;
                v = VV[lane + 64];
                acc0 += w2.x*v.x + w2.y*v.y + w2.z*v.z + w2.w*v.w;
            }
            {   // k=3 : straddle at lane 16 (elements 448..451)
                float4 v = VV[lane + 96];
                float dlo = w3.x*v.x + w3.y*v.y;
                float dhi = w3.z*v.z + w3.w*v.w;
                if (lane < 16)       acc0 += dlo + dhi;
                else if (lane == 16) { acc0 += dlo; acc1 += dhi; }
                else                 acc1 += dlo + dhi;
            }
            {   // k=4..6 : pure row1
                float4 v = VV[lane + 128];
                acc1 += w4.x*v.x + w4.y*v.y + w4.z*v.z + w4.w*v.w;
                v = VV[lane + 160];
                acc1 += w5.x*v.x + w5.y*v.y + w5.z*v.z + w5.w*v.w;
                v = VV[lane + 192];
                acc1 += w6.x*v.x + w6.y*v.y + w6.z*v.z + w6.w*v.w;
            }
            if (lane == 0) {  // tail float4 idx 224 = elements 896..899 (row1)
                float4 v = VV[224];
                acc1 += wt.x*v.x + wt.y*v.y + wt.z*v.z + wt.w*v.w;
            }
            #pragma unroll
            for (int o = 16; o; o >>= 1) {
                acc0 += __shfl_xor_sync(0xFFFFFFFFu, acc0, o);
                acc1 += __shfl_xor_sync(0xFFFFFFFFu, acc1, o);
            }
            if (lane == 0) {
                const float2 b2 = __ldg(reinterpret_cast<const float2*>(db2) + pr);
                float2 o2;
                o2.x = acc0 + b2.x;
                o2.y = acc1 + b2.y;
                *(reinterpret_cast<float2*>(out) + pr) = o2;
            }
        }
    }
}

// ---------------------------------------------------------------------------
// Inputs: x, t, TwE, PE, CE, mE, ext_W1, ext_b1, ext_W2, ext_b2,
//         dec_W1, dec_b1, dec_W2, dec_b2
// ---------------------------------------------------------------------------
extern "C" void kernel_launch(void* const* d_in, const int* in_sizes, int n_in,
                              void* d_out, int out_size)
{
    const float* x   = (const float*)d_in[0];
    const float* TwE = (const float*)d_in[2];
    const float* PE  = (const float*)d_in[3];
    const float* CE  = (const float*)d_in[4];
    const float* mE  = (const float*)d_in[5];
    const float* eW1 = (const float*)d_in[6];
    const float* eb1 = (const float*)d_in[7];
    const float* eW2 = (const float*)d_in[8];
    const float* eb2 = (const float*)d_in[9];
    const float* dW1 = (const float*)d_in[10];
    const float* db1 = (const float*)d_in[11];
    const float* dW2 = (const float*)d_in[12];
    const float* db2 = (const float*)d_in[13];
    float* out = (float*)d_out;

    const int xoff = in_sizes[0] - 4 * 256 * 128;

    fused_kernel<<<NBLK, NTHR>>>(x, TwE, PE, CE, mE,
                                 eW1, eb1, eW2, eb2,
                                 dW1, db1, dW2, db2,
                                 out, xoff);
    (void)n_in; (void)out_size;
}

// round 5
// speedup vs baseline: 1.0021x; 1.0021x over previous
#include <cuda_runtime.h>
#include <cstddef>

#define NBLK   148
#define NTHR   1024
#define NWARPS (NBLK * 32)       // 4736
#define NPAIRS 65536             // 131072 rows / 2
#define MDIM   450

// Scratch (device globals; no allocation)
__device__ __align__(16) float g_Fpart[128 * 128];
__device__ __align__(16) float g_feat[452];
__device__ __align__(16) float g_h[452];
__device__ __align__(16) float g_feat2[452];
__device__ __align__(16) float g_h2[452];

// Grid barrier (monotonic generation -> graph-replay safe)
__device__ unsigned g_count = 0;
__device__ volatile unsigned g_gen = 0;

__device__ __forceinline__ void grid_bar()
{
    __syncthreads();
    if (threadIdx.x == 0) {
        const unsigned gen = g_gen;
        __threadfence();
        if (atomicAdd(&g_count, 1u) == (unsigned)gridDim.x - 1u) {
            atomicExch(&g_count, 0u);
            __threadfence();
            g_gen = gen + 1u;
        } else {
            while (g_gen == gen) { }
            __threadfence();
        }
    }
    __syncthreads();
}

// L2 prefetch helper: each calling thread touches nlines lines, strided.
__device__ __forceinline__ void l2_pf(const float* base, size_t line0,
                                      size_t my, size_t nthreads, int nlines)
{
    const char* p = (const char*)base;
    #pragma unroll
    for (int k = 0; k < 16; ++k) {
        if (k >= nlines) break;
        size_t line = line0 + my + (size_t)k * nthreads;
        asm volatile("prefetch.global.L2 [%0];" :: "l"(p + line * 128));
    }
}

// Warp-per-row 450x450 matvec: vout = [relu](W @ vin + b). Blocks 0..14.
__device__ __forceinline__ void mv450_stage(const float* __restrict__ W,
                                            const float* __restrict__ b,
                                            const float* __restrict__ vin_g,
                                            float* __restrict__ vout_g,
                                            bool do_relu, float* sh)
{
    const int tid = threadIdx.x;
    if (tid < MDIM) sh[tid] = __ldcg(vin_g + tid);
    __syncthreads();

    const int wid  = tid >> 5;
    const int lane = tid & 31;
    const int row  = blockIdx.x * 32 + wid;
    if (row < MDIM) {
        const float2* wr = reinterpret_cast<const float2*>(W + (size_t)row * MDIM);
        const float2* sv = reinterpret_cast<const float2*>(sh);
        float acc = 0.f;
        #pragma unroll
        for (int j = 0; j < 7; ++j) {
            const float2 w = __ldg(wr + lane + 32 * j);
            const float2 v = sv[lane + 32 * j];
            acc += w.x * v.x + w.y * v.y;
        }
        if (lane == 0) {
            const float2 w = __ldg(wr + 224);
            const float2 v = sv[224];
            acc += w.x * v.x + w.y * v.y;
        }
        #pragma unroll
        for (int o = 16; o; o >>= 1) acc += __shfl_xor_sync(0xFFFFFFFFu, acc, o);
        if (lane == 0) {
            float r = acc + __ldg(b + row);
            vout_g[row] = do_relu ? fmaxf(r, 0.f) : r;
        }
    }
}

__global__ void __launch_bounds__(NTHR, 1)
fused_kernel(const float* __restrict__ x,   const float* __restrict__ TwE,
             const float* __restrict__ PE,  const float* __restrict__ CE,
             const float* __restrict__ mE,
             const float* __restrict__ eW1, const float* __restrict__ eb1,
             const float* __restrict__ eW2, const float* __restrict__ eb2,
             const float* __restrict__ dW1, const float* __restrict__ db1,
             const float* __restrict__ dW2, const float* __restrict__ db2,
             float* __restrict__ out, int xoff)
{
    __shared__ float sh[10240];            // 40KB, reused per stage
    const int tid  = threadIdx.x;
    const int wid  = tid >> 5;
    const int lane = tid & 31;
    const int blk  = blockIdx.x;

    // ===== Stage 1: f partials. 128 blocks x 8 tp-rows each. =====
    // Warp = (row-pair, c-chunk): pr = wid&3 (rows 2pr,2pr+1), ch = wid>>2 (16 c's).
    if (blk < 128) {
        float* sx = sh;                    // [8][128] x rows
        float* sp = sh + 1024;             // [8 chunks][8 rows][128 i]
        sx[tid] = x[xoff + blk * 1024 + tid];
        __syncthreads();

        const int pr = wid & 3;
        const int ch = wid >> 2;
        const int i0 = lane * 4;
        const int r0 = pr * 2, r1 = r0 + 1;
        float4 a0 = {0,0,0,0}, a1 = {0,0,0,0};
        const int cb = ch * 16;
        #pragma unroll
        for (int cc = 0; cc < 16; ++cc) {
            const int c = cb + cc;
            const float4 ce = *reinterpret_cast<const float4*>(CE + c * 128 + i0);
            const float x0 = sx[r0 * 128 + c];
            const float x1 = sx[r1 * 128 + c];
            a0.x += x0 * ce.x; a0.y += x0 * ce.y; a0.z += x0 * ce.z; a0.w += x0 * ce.w;
            a1.x += x1 * ce.x; a1.y += x1 * ce.y; a1.z += x1 * ce.z; a1.w += x1 * ce.w;
        }
        *reinterpret_cast<float4*>(sp + (ch * 8 + r0) * 128 + i0) = a0;
        *reinterpret_cast<float4*>(sp + (ch * 8 + r1) * 128 + i0) = a1;
        __syncthreads();

        const int row = tid >> 7;          // 0..7
        const int i   = tid & 127;
        float s = 0.f;
        #pragma unroll
        for (int c2 = 0; c2 < 8; ++c2) s += sp[(c2 * 8 + row) * 128 + i];
        const int gr = blk * 8 + row;      // tp index
        const int t  = gr >> 8;
        const int p  = gr & 255;
        s *= __ldg(PE + p * 128 + i) * __ldg(TwE + t * 128 + i);
        __syncthreads();
        sh[tid] = s;                       // [row][i]
        __syncthreads();
        if (tid < 128) {
            float t2 = 0.f;
            #pragma unroll
            for (int r = 0; r < 8; ++r) t2 += sh[r * 128 + tid];
            g_Fpart[blk * 128 + tid] = t2;
        }
    } else {
        // Prefetch phase 0: dec_W2 lines [0, 20480*12) = 31.4MB
        l2_pf(dW2, 0, (size_t)(blk - 128) * NTHR + tid, 20480u * 32, 12);
    }
    grid_bar();

    // ===== Stage 2: feat = mE @ f (blocks 0..14) =====
    if (blk < 15) {
        if (tid < 128) {
            float s = 0.f;
            #pragma unroll 8
            for (int b = 0; b < 128; ++b) s += __ldcg(&g_Fpart[b * 128 + tid]);
            sh[tid] = s;
        }
        __syncthreads();
        const int row = blk * 32 + wid;
        if (row < MDIM) {
            const float* r = mE + row * 128;
            float acc = __ldg(r + lane)       * sh[lane]
                      + __ldg(r + lane + 32)  * sh[lane + 32]
                      + __ldg(r + lane + 64)  * sh[lane + 64]
                      + __ldg(r + lane + 96)  * sh[lane + 96];
            #pragma unroll
            for (int o = 16; o; o >>= 1) acc += __shfl_xor_sync(0xFFFFFFFFu, acc, o);
            if (lane == 0) g_feat[row] = acc;
        }
    } else {
        // Prefetch phase 1: next ~34.8MB
        l2_pf(dW2, 245760, (size_t)(blk - 15) * NTHR + tid, 136192u, 2);
    }
    grid_bar();

    // ===== Stages 3..5: 450x450 chain (blocks 0..14) =====
    if (blk < 15) mv450_stage(eW1, eb1, g_feat, g_h, true, sh);
    else l2_pf(dW2, 518144, (size_t)(blk - 15) * NTHR + tid, 136192u, 2); // ~+34.8MB
    grid_bar();
    if (blk < 15) mv450_stage(eW2, eb2, g_h, g_feat2, false, sh);
    grid_bar();
    if (blk < 15) mv450_stage(dW1, db1, g_feat2, g_h2, true, sh);
    grid_bar();

    // ===== Stage 6: out = dec_W2 @ h2 + db2 (131072 x 450) =====
    // Warp processes a row-pair as one contiguous 3600B segment:
    // 225 float4 per pair; lane j reads float4 idx lane+32k (k=0..6), lane0 reads 224.
    // v duplicated in smem: svv = h2 || h2 (900 floats) -> float4-aligned gathers.
    {
        for (int i = tid; i < 900; i += NTHR)
            sh[i] = __ldcg(&g_h2[(i < 450) ? i : (i - 450)]);
        __syncthreads();
        const float4* VV = reinterpret_cast<const float4*>(sh);
        const int gw = blk * 32 + wid;

        for (int pr = gw; pr < NPAIRS; pr += NWARPS) {
            const float4* wr = reinterpret_cast<const float4*>(dW2 + (size_t)pr * 900);
            float4 w0 = __ldcs(wr + lane);
            float4 w1 = __ldcs(wr + lane + 32);
            float4 w2 = __ldcs(wr + lane + 64);
            float4 w3 = __ldcs(wr + lane + 96);
            float4 w4 = __ldcs(wr + lane + 128);
            float4 w5 = __ldcs(wr + lane + 160);
            float4 w6 = __ldcs(wr + lane + 192);
            float4 wt;
            if (lane == 0) wt = __ldcs(wr + 224);

            float acc0 = 0.f, acc1 = 0.f;
            {   // k=0..2 : pure row0 (elements < 448)
                float4 v = VV[lane];
                acc0 += w0.x*v.x + w0.y*v.y + w0.z*v.z + w0.w*v.w;
                v = VV[lane + 32];
                acc0 += w1.x*v.x + w1.y*v.y + w1.z*v.z + w1.w*v.w;
                v = VV[lane + 64];
                acc0 += w2.x*v.x + w2.y*v.y + w2.z*v.z + w2.w*v.w;
            }
            {   // k=3 : straddle at lane 16 (elements 448..451)
                float4 v = VV[lane + 96];
                float dlo = w3.x*v.x + w3.y*v.y;
                float dhi = w3.z*v.z + w3.w*v.w;
                if (lane < 16)       acc0 += dlo + dhi;
                else if (lane == 16) { acc0 += dlo; acc1 += dhi; }
                else                 acc1 += dlo + dhi;
            }
            {   // k=4..6 : pure row1
                float4 v = VV[lane + 128];
                acc1 += w4.x*v.x + w4.y*v.y + w4.z*v.z + w4.w*v.w;
                v = VV[lane + 160];
                acc1 += w5.x*v.x + w5.y*v.y + w5.z*v.z + w5.w*v.w;
                v = VV[lane + 192];
                acc1 += w6.x*v.x + w6.y*v.y + w6.z*v.z + w6.w*v.w;
            }
            if (lane == 0) {  // tail float4 idx 224 = elements 896..899 (row1)
                float4 v = VV[224];
                acc1 += wt.x*v.x + wt.y*v.y + wt.z*v.z + wt.w*v.w;
            }
            #pragma unroll
            for (int o = 16; o; o >>= 1) {
                acc0 += __shfl_xor_sync(0xFFFFFFFFu, acc0, o);
                acc1 += __shfl_xor_sync(0xFFFFFFFFu, acc1, o);
            }
            if (lane == 0) {
                const float2 b2 = __ldg(reinterpret_cast<const float2*>(db2) + pr);
                float2 o2;
                o2.x = acc0 + b2.x;
                o2.y = acc1 + b2.y;
                *(reinterpret_cast<float2*>(out) + pr) = o2;
            }
        }
    }
}

// ---------------------------------------------------------------------------
// Inputs: x, t, TwE, PE, CE, mE, ext_W1, ext_b1, ext_W2, ext_b2,
//         dec_W1, dec_b1, dec_W2, dec_b2
// ---------------------------------------------------------------------------
extern "C" void kernel_launch(void* const* d_in, const int* in_sizes, int n_in,
                              void* d_out, int out_size)
{
    const float* x   = (const float*)d_in[0];
    const float* TwE = (const float*)d_in[2];
    const float* PE  = (const float*)d_in[3];
    const float* CE  = (const float*)d_in[4];
    const float* mE  = (const float*)d_in[5];
    const float* eW1 = (const float*)d_in[6];
    const float* eb1 = (const float*)d_in[7];
    const float* eW2 = (const float*)d_in[8];
    const float* eb2 = (const float*)d_in[9];
    const float* dW1 = (const float*)d_in[10];
    const float* db1 = (const float*)d_in[11];
    const float* dW2 = (const float*)d_in[12];
    const float* db2 = (const float*)d_in[13];
    float* out = (float*)d_out;

    const int xoff = in_sizes[0] - 4 * 256 * 128;

    fused_kernel<<<NBLK, NTHR>>>(x, TwE, PE, CE, mE,
                                 eW1, eb1, eW2, eb2,
                                 dW1, db1, dW2, db2,
                                 out, xoff);
    (void)n_in; (void)out_size;
}

// round 6
// speedup vs baseline: 1.0056x; 1.0034x over previous
#include <cuda_runtime.h>
#include <cstddef>

#define NBLK   148
#define NTHR   1024
#define NWARPS (NBLK * 32)       // 4736
#define NPAIRS 65536             // 131072 rows / 2
#define MDIM   450

// Scratch (device globals; no allocation)
__device__ __align__(16) float g_Fpart[128 * 128];
__device__ __align__(16) float g_feat[452];
__device__ __align__(16) float g_h[452];
__device__ __align__(16) float g_feat2[452];
__device__ __align__(16) float g_h2[452];

// Grid barrier (monotonic generation -> graph-replay safe)
__device__ unsigned g_count = 0;
__device__ volatile unsigned g_gen = 0;

__device__ __forceinline__ void grid_bar()
{
    __syncthreads();
    if (threadIdx.x == 0) {
        const unsigned gen = g_gen;
        __threadfence();
        if (atomicAdd(&g_count, 1u) == (unsigned)gridDim.x - 1u) {
            atomicExch(&g_count, 0u);
            __threadfence();
            g_gen = gen + 1u;
        } else {
            while (g_gen == gen) { }
            __threadfence();
        }
    }
    __syncthreads();
}

// L2 prefetch helper: each calling thread touches nlines lines, strided.
__device__ __forceinline__ void l2_pf(const float* base, size_t line0,
                                      size_t my, size_t nthreads, int nlines)
{
    const char* p = (const char*)base;
    #pragma unroll
    for (int k = 0; k < 16; ++k) {
        if (k >= nlines) break;
        size_t line = line0 + my + (size_t)k * nthreads;
        asm volatile("prefetch.global.L2 [%0];" :: "l"(p + line * 128));
    }
}

// Warp-per-row 450x450 matvec: vout = [relu](W @ vin + b). Blocks 0..14.
__device__ __forceinline__ void mv450_stage(const float* __restrict__ W,
                                            const float* __restrict__ b,
                                            const float* __restrict__ vin_g,
                                            float* __restrict__ vout_g,
                                            bool do_relu, float* sh)
{
    const int tid = threadIdx.x;
    if (tid < MDIM) sh[tid] = __ldcg(vin_g + tid);
    __syncthreads();

    const int wid  = tid >> 5;
    const int lane = tid & 31;
    const int row  = blockIdx.x * 32 + wid;
    if (row < MDIM) {
        const float2* wr = reinterpret_cast<const float2*>(W + (size_t)row * MDIM);
        const float2* sv = reinterpret_cast<const float2*>(sh);
        float acc = 0.f;
        #pragma unroll
        for (int j = 0; j < 7; ++j) {
            const float2 w = __ldg(wr + lane + 32 * j);
            const float2 v = sv[lane + 32 * j];
            acc += w.x * v.x + w.y * v.y;
        }
        if (lane == 0) {
            const float2 w = __ldg(wr + 224);
            const float2 v = sv[224];
            acc += w.x * v.x + w.y * v.y;
        }
        #pragma unroll
        for (int o = 16; o; o >>= 1) acc += __shfl_xor_sync(0xFFFFFFFFu, acc, o);
        if (lane == 0) {
            float r = acc + __ldg(b + row);
            vout_g[row] = do_relu ? fmaxf(r, 0.f) : r;
        }
    }
}

__global__ void __launch_bounds__(NTHR, 1)
fused_kernel(const float* __restrict__ x,   const float* __restrict__ TwE,
             const float* __restrict__ PE,  const float* __restrict__ CE,
             const float* __restrict__ mE,
             const float* __restrict__ eW1, const float* __restrict__ eb1,
             const float* __restrict__ eW2, const float* __restrict__ eb2,
             const float* __restrict__ dW1, const float* __restrict__ db1,
             const float* __restrict__ dW2, const float* __restrict__ db2,
             float* __restrict__ out, int xoff)
{
    __shared__ float sh[10240];            // 40KB, reused per stage
    const int tid  = threadIdx.x;
    const int wid  = tid >> 5;
    const int lane = tid & 31;
    const int blk  = blockIdx.x;

    // ===== Stage 1: f partials. 128 blocks x 8 tp-rows each. =====
    // Warp = (row-pair, c-chunk): pr = wid&3 (rows 2pr,2pr+1), ch = wid>>2 (16 c's).
    if (blk < 128) {
        float* sx = sh;                    // [8][128] x rows
        float* sp = sh + 1024;             // [8 chunks][8 rows][128 i]
        sx[tid] = x[xoff + blk * 1024 + tid];
        __syncthreads();

        const int pr = wid & 3;
        const int ch = wid >> 2;
        const int i0 = lane * 4;
        const int r0 = pr * 2, r1 = r0 + 1;
        float4 a0 = {0,0,0,0}, a1 = {0,0,0,0};
        const int cb = ch * 16;
        #pragma unroll
        for (int cc = 0; cc < 16; ++cc) {
            const int c = cb + cc;
            const float4 ce = *reinterpret_cast<const float4*>(CE + c * 128 + i0);
            const float x0 = sx[r0 * 128 + c];
            const float x1 = sx[r1 * 128 + c];
            a0.x += x0 * ce.x; a0.y += x0 * ce.y; a0.z += x0 * ce.z; a0.w += x0 * ce.w;
            a1.x += x1 * ce.x; a1.y += x1 * ce.y; a1.z += x1 * ce.z; a1.w += x1 * ce.w;
        }
        *reinterpret_cast<float4*>(sp + (ch * 8 + r0) * 128 + i0) = a0;
        *reinterpret_cast<float4*>(sp + (ch * 8 + r1) * 128 + i0) = a1;
        __syncthreads();

        const int row = tid >> 7;          // 0..7
        const int i   = tid & 127;
        float s = 0.f;
        #pragma unroll
        for (int c2 = 0; c2 < 8; ++c2) s += sp[(c2 * 8 + row) * 128 + i];
        const int gr = blk * 8 + row;      // tp index
        const int t  = gr >> 8;
        const int p  = gr & 255;
        s *= __ldg(PE + p * 128 + i) * __ldg(TwE + t * 128 + i);
        __syncthreads();
        sh[tid] = s;                       // [row][i]
        __syncthreads();
        if (tid < 128) {
            float t2 = 0.f;
            #pragma unroll
            for (int r = 0; r < 8; ++r) t2 += sh[r * 128 + tid];
            g_Fpart[blk * 128 + tid] = t2;
        }
    } else {
        // Prefetch phase 0: dec_W2 lines [0, 20480*12) = 31.4MB
        l2_pf(dW2, 0, (size_t)(blk - 128) * NTHR + tid, 20480u * 32, 12);
    }
    grid_bar();

    // ===== Stage 2: feat = mE @ f (blocks 0..14) =====
    if (blk < 15) {
        if (tid < 128) {
            float s = 0.f;
            #pragma unroll 8
            for (int b = 0; b < 128; ++b) s += __ldcg(&g_Fpart[b * 128 + tid]);
            sh[tid] = s;
        }
        __syncthreads();
        const int row = blk * 32 + wid;
        if (row < MDIM) {
            const float* r = mE + row * 128;
            float acc = __ldg(r + lane)       * sh[lane]
                      + __ldg(r + lane + 32)  * sh[lane + 32]
                      + __ldg(r + lane + 64)  * sh[lane + 64]
                      + __ldg(r + lane + 96)  * sh[lane + 96];
            #pragma unroll
            for (int o = 16; o; o >>= 1) acc += __shfl_xor_sync(0xFFFFFFFFu, acc, o);
            if (lane == 0) g_feat[row] = acc;
        }
    } else {
        // Prefetch phase 1: next ~34.8MB
        l2_pf(dW2, 245760, (size_t)(blk - 15) * NTHR + tid, 136192u, 2);
    }
    grid_bar();

    // ===== Stages 3..5: 450x450 chain (blocks 0..14) =====
    if (blk < 15) mv450_stage(eW1, eb1, g_feat, g_h, true, sh);
    else l2_pf(dW2, 518144, (size_t)(blk - 15) * NTHR + tid, 136192u, 2); // ~+34.8MB
    grid_bar();
    if (blk < 15) mv450_stage(eW2, eb2, g_h, g_feat2, false, sh);
    grid_bar();
    if (blk < 15) mv450_stage(dW1, db1, g_feat2, g_h2, true, sh);
    grid_bar();

    // ===== Stage 6: out = dec_W2 @ h2 + db2 (131072 x 450) =====
    // Warp processes a row-pair as one contiguous 3600B segment:
    // 225 float4 per pair; lane j reads float4 idx lane+32k (k=0..6), lane0 reads 224.
    // v duplicated in smem: svv = h2 || h2 (900 floats) -> float4-aligned gathers.
    {
        for (int i = tid; i < 900; i += NTHR)
            sh[i] = __ldcg(&g_h2[(i < 450) ? i : (i - 450)]);
        __syncthreads();
        const float4* VV = reinterpret_cast<const float4*>(sh);
        const int gw = blk * 32 + wid;

        for (int pr = gw; pr < NPAIRS; pr += NWARPS) {
            const float4* wr = reinterpret_cast<const float4*>(dW2 + (size_t)pr * 900);
            float4 w0 = __ldcs(wr + lane);
            float4 w1 = __ldcs(wr + lane + 32);
            float4 w2 = __ldcs(wr + lane + 64);
            float4 w3 = __ldcs(wr + lane + 96);
            float4 w4 = __ldcs(wr + lane + 128);
            float4 w5 = __ldcs(wr + lane + 160);
            float4 w6 = __ldcs(wr + lane + 192);
            float4 wt;
            if (lane == 0) wt = __ldcs(wr + 224);

            float acc0 = 0.f, acc1 = 0.f;
            {   // k=0..2 : pure row0 (elements < 448)
                float4 v = VV[lane];
                acc0 += w0.x*v.x + w0.y*v.y + w0.z*v.z + w0.w*v.w;
                v = VV[lane + 32];
                acc0 += w1.x*v.x + w1.y*v.y + w1.z*v.z + w1.w*v.w;
                v = VV[lane + 64];
                acc0 += w2.x*v.x + w2.y*v.y + w2.z*v.z + w2.w*v.w;
            }
            {   // k=3 : straddle at lane 16 (elements 448..451)
                float4 v = VV[lane + 96];
                float dlo = w3.x*v.x + w3.y*v.y;
                float dhi = w3.z*v.z + w3.w*v.w;
                if (lane < 16)       acc0 += dlo + dhi;
                else if (lane == 16) { acc0 += dlo; acc1 += dhi; }
                else                 acc1 += dlo + dhi;
            }
            {   // k=4..6 : pure row1
                float4 v = VV[lane + 128];
                acc1 += w4.x*v.x + w4.y*v.y + w4.z*v.z + w4.w*v.w;
                v = VV[lane + 160];
                acc1 += w5.x*v.x + w5.y*v.y + w5.z*v.z + w5.w*v.w;
                v = VV[lane + 192];
                acc1 += w6.x*v.x + w6.y*v.y + w6.z*v.z + w6.w*v.w;
            }
            if (lane == 0) {  // tail float4 idx 224 = elements 896..899 (row1)
                float4 v = VV[224];
                acc1 += wt.x*v.x + wt.y*v.y + wt.z*v.z + wt.w*v.w;
            }
            #pragma unroll
            for (int o = 16; o; o >>= 1) {
                acc0 += __shfl_xor_sync(0xFFFFFFFFu, acc0, o);
                acc1 += __shfl_xor_sync(0xFFFFFFFFu, acc1, o);
            }
            if (lane == 0) {
                const float2 b2 = __ldg(reinterpret_cast<const float2*>(db2) + pr);
                float2 o2;
                o2.x = acc0 + b2.x;
                o2.y = acc1 + b2.y;
                *(reinterpret_cast<float2*>(out) + pr) = o2;
            }
        }
    }
}

// ---------------------------------------------------------------------------
// Inputs: x, t, TwE, PE, CE, mE, ext_W1, ext_b1, ext_W2, ext_b2,
//         dec_W1, dec_b1, dec_W2, dec_b2
// ---------------------------------------------------------------------------
extern "C" void kernel_launch(void* const* d_in, const int* in_sizes, int n_in,
                              void* d_out, int out_size)
{
    const float* x   = (const float*)d_in[0];
    const float* TwE = (const float*)d_in[2];
    const float* PE  = (const float*)d_in[3];
    const float* CE  = (const float*)d_in[4];
    const float* mE  = (const float*)d_in[5];
    const float* eW1 = (const float*)d_in[6];
    const float* eb1 = (const float*)d_in[7];
    const float* eW2 = (const float*)d_in[8];
    const float* eb2 = (const float*)d_in[9];
    const float* dW1 = (const float*)d_in[10];
    const float* db1 = (const float*)d_in[11];
    const float* dW2 = (const float*)d_in[12];
    const float* db2 = (const float*)d_in[13];
    float* out = (float*)d_out;

    const int xoff = in_sizes[0] - 4 * 256 * 128;

    fused_kernel<<<NBLK, NTHR>>>(x, TwE, PE, CE, mE,
                                 eW1, eb1, eW2, eb2,
                                 dW1, db1, dW2, db2,
                                 out, xoff);
    (void)n_in; (void)out_size;
}

// round 7
// speedup vs baseline: 9.8753x; 9.8208x over previous
#include <cuda_runtime.h>
#include <cstddef>

#define NBLK   148
#define NTHR   1024
#define NWARPS (NBLK * 32)       // 4736
#define NPAIRS 65536             // 131072 rows / 2
#define MDIM   450

// Scratch (device globals; no allocation)
__device__ __align__(16) float g_Fpart[128 * 128];
__device__ __align__(16) float g_feat[452];
__device__ __align__(16) float g_h[452];
__device__ __align__(16) float g_feat2[452];
__device__ __align__(16) float g_h2[452];

// Grid barrier (monotonic generation -> graph-replay safe)
__device__ unsigned g_count = 0;
__device__ volatile unsigned g_gen = 0;

__device__ __forceinline__ void grid_bar()
{
    __syncthreads();
    if (threadIdx.x == 0) {
        const unsigned gen = g_gen;
        __threadfence();
        if (atomicAdd(&g_count, 1u) == (unsigned)gridDim.x - 1u) {
            atomicExch(&g_count, 0u);
            __threadfence();
            g_gen = gen + 1u;
        } else {
            while (g_gen == gen) { }
            __threadfence();
        }
    }
    __syncthreads();
}

// Warp-per-row 450x450 matvec: vout = [relu](W @ vin + b). Blocks 0..14.
__device__ __forceinline__ void mv450_stage(const float* __restrict__ W,
                                            const float* __restrict__ b,
                                            const float* __restrict__ vin_g,
                                            float* __restrict__ vout_g,
                                            bool do_relu, float* sh)
{
    const int tid = threadIdx.x;
    if (tid < MDIM) sh[tid] = __ldcg(vin_g + tid);
    __syncthreads();

    const int wid  = tid >> 5;
    const int lane = tid & 31;
    const int row  = blockIdx.x * 32 + wid;
    if (row < MDIM) {
        const float2* wr = reinterpret_cast<const float2*>(W + (size_t)row * MDIM);
        const float2* sv = reinterpret_cast<const float2*>(sh);
        float acc = 0.f;
        #pragma unroll
        for (int j = 0; j < 7; ++j) {
            const float2 w = __ldg(wr + lane + 32 * j);
            const float2 v = sv[lane + 32 * j];
            acc += w.x * v.x + w.y * v.y;
        }
        if (lane == 0) {
            const float2 w = __ldg(wr + 224);
            const float2 v = sv[224];
            acc += w.x * v.x + w.y * v.y;
        }
        #pragma unroll
        for (int o = 16; o; o >>= 1) acc += __shfl_xor_sync(0xFFFFFFFFu, acc, o);
        if (lane == 0) {
            float r = acc + __ldg(b + row);
            vout_g[row] = do_relu ? fmaxf(r, 0.f) : r;
        }
    }
}

__global__ void __launch_bounds__(NTHR, 1)
fused_kernel(const float* __restrict__ x,   const float* __restrict__ TwE,
             const float* __restrict__ PE,  const float* __restrict__ CE,
             const float* __restrict__ mE,
             const float* __restrict__ eW1, const float* __restrict__ eb1,
             const float* __restrict__ eW2, const float* __restrict__ eb2,
             const float* __restrict__ dW1, const float* __restrict__ db1,
             const float* __restrict__ dW2, const float* __restrict__ db2,
             float* __restrict__ out, int xoff)
{
    __shared__ float sh[10240];            // 40KB, reused per stage
    const int tid  = threadIdx.x;
    const int wid  = tid >> 5;
    const int lane = tid & 31;
    const int blk  = blockIdx.x;

    // ===== Stage 1: f partials. 128 blocks x 8 tp-rows each. =====
    // Warp = (row-pair, c-chunk): pr = wid&3 (rows 2pr,2pr+1), ch = wid>>2 (16 c's).
    if (blk < 128) {
        float* sx = sh;                    // [8][128] x rows
        float* sp = sh + 1024;             // [8 chunks][8 rows][128 i]
        sx[tid] = x[xoff + blk * 1024 + tid];
        __syncthreads();

        const int pr = wid & 3;
        const int ch = wid >> 2;
        const int i0 = lane * 4;
        const int r0 = pr * 2, r1 = r0 + 1;
        float4 a0 = {0,0,0,0}, a1 = {0,0,0,0};
        const int cb = ch * 16;
        #pragma unroll
        for (int cc = 0; cc < 16; ++cc) {
            const int c = cb + cc;
            const float4 ce = *reinterpret_cast<const float4*>(CE + c * 128 + i0);
            const float x0 = sx[r0 * 128 + c];
            const float x1 = sx[r1 * 128 + c];
            a0.x += x0 * ce.x; a0.y += x0 * ce.y; a0.z += x0 * ce.z; a0.w += x0 * ce.w;
            a1.x += x1 * ce.x; a1.y += x1 * ce.y; a1.z += x1 * ce.z; a1.w += x1 * ce.w;
        }
        *reinterpret_cast<float4*>(sp + (ch * 8 + r0) * 128 + i0) = a0;
        *reinterpret_cast<float4*>(sp + (ch * 8 + r1) * 128 + i0) = a1;
        __syncthreads();

        const int row = tid >> 7;          // 0..7
        const int i   = tid & 127;
        float s = 0.f;
        #pragma unroll
        for (int c2 = 0; c2 < 8; ++c2) s += sp[(c2 * 8 + row) * 128 + i];
        const int gr = blk * 8 + row;      // tp index
        const int t  = gr >> 8;
        const int p  = gr & 255;
        s *= __ldg(PE + p * 128 + i) * __ldg(TwE + t * 128 + i);
        __syncthreads();
        sh[tid] = s;                       // [row][i]
        __syncthreads();
        if (tid < 128) {
            float t2 = 0.f;
            #pragma unroll
            for (int r = 0; r < 8; ++r) t2 += sh[r * 128 + tid];
            g_Fpart[blk * 128 + tid] = t2;
        }
    }
    grid_bar();

    // ===== Stage 2: feat = mE @ f (blocks 0..14) =====
    if (blk < 15) {
        if (tid < 128) {
            float s = 0.f;
            #pragma unroll 8
            for (int b = 0; b < 128; ++b) s += __ldcg(&g_Fpart[b * 128 + tid]);
            sh[tid] = s;
        }
        __syncthreads();
        const int row = blk * 32 + wid;
        if (row < MDIM) {
            const float* r = mE + row * 128;
            float acc = __ldg(r + lane)       * sh[lane]
                      + __ldg(r + lane + 32)  * sh[lane + 32]
                      + __ldg(r + lane + 64)  * sh[lane + 64]
                      + __ldg(r + lane + 96)  * sh[lane + 96];
            #pragma unroll
            for (int o = 16; o; o >>= 1) acc += __shfl_xor_sync(0xFFFFFFFFu, acc, o);
            if (lane == 0) g_feat[row] = acc;
        }
    }
    grid_bar();

    // ===== Stages 3..5: 450x450 chain (blocks 0..14) =====
    if (blk < 15) mv450_stage(eW1, eb1, g_feat, g_h, true, sh);
    grid_bar();
    if (blk < 15) mv450_stage(eW2, eb2, g_h, g_feat2, false, sh);
    grid_bar();
    if (blk < 15) mv450_stage(dW1, db1, g_feat2, g_h2, true, sh);
    grid_bar();

    // ===== Stage 6: out = dec_W2 @ h2 + db2 (131072 x 450) =====
    // Warp processes a row-pair as one contiguous 3600B segment:
    // 225 float4 per pair; lane j reads float4 idx lane+32k (k=0..6), lane0 reads 224.
    // v duplicated in smem: svv = h2 || h2 (900 floats) -> float4-aligned gathers.
    {
        for (int i = tid; i < 900; i += NTHR)
            sh[i] = __ldcg(&g_h2[(i < 450) ? i : (i - 450)]);
        __syncthreads();
        const float4* VV = reinterpret_cast<const float4*>(sh);
        const int gw = blk * 32 + wid;

        for (int pr = gw; pr < NPAIRS; pr += NWARPS) {
            const float4* wr = reinterpret_cast<const float4*>(dW2 + (size_t)pr * 900);
            float4 w0 = __ldcs(wr + lane);
            float4 w1 = __ldcs(wr + lane + 32);
            float4 w2 = __ldcs(wr + lane + 64);
            float4 w3 = __ldcs(wr + lane + 96);
            float4 w4 = __ldcs(wr + lane + 128);
            float4 w5 = __ldcs(wr + lane + 160);
            float4 w6 = __ldcs(wr + lane + 192);
            float4 wt;
            if (lane == 0) wt = __ldcs(wr + 224);

            float acc0 = 0.f, acc1 = 0.f;
            {   // k=0..2 : pure row0 (elements < 448)
                float4 v = VV[lane];
                acc0 += w0.x*v.x + w0.y*v.y + w0.z*v.z + w0.w*v.w;
                v = VV[lane + 32];
                acc0 += w1.x*v.x + w1.y*v.y + w1.z*v.z + w1.w*v.w;
                v = VV[lane + 64];
                acc0 += w2.x*v.x + w2.y*v.y + w2.z*v.z + w2.w*v.w;
            }
            {   // k=3 : straddle at lane 16 (elements 448..451)
                float4 v = VV[lane + 96];
                float dlo = w3.x*v.x + w3.y*v.y;
                float dhi = w3.z*v.z + w3.w*v.w;
                if (lane < 16)       acc0 += dlo + dhi;
                else if (lane == 16) { acc0 += dlo; acc1 += dhi; }
                else                 acc1 += dlo + dhi;
            }
            {   // k=4..6 : pure row1
                float4 v = VV[lane + 128];
                acc1 += w4.x*v.x + w4.y*v.y + w4.z*v.z + w4.w*v.w;
                v = VV[lane + 160];
                acc1 += w5.x*v.x + w5.y*v.y + w5.z*v.z + w5.w*v.w;
                v = VV[lane + 192];
                acc1 += w6.x*v.x + w6.y*v.y + w6.z*v.z + w6.w*v.w;
            }
            if (lane == 0) {  // tail float4 idx 224 = elements 896..899 (row1)
                float4 v = VV[224];
                acc1 += wt.x*v.x + wt.y*v.y + wt.z*v.z + wt.w*v.w;
            }
            #pragma unroll
            for (int o = 16; o; o >>= 1) {
                acc0 += __shfl_xor_sync(0xFFFFFFFFu, acc0, o);
                acc1 += __shfl_xor_sync(0xFFFFFFFFu, acc1, o);
            }
            if (lane == 0) {
                const float2 b2 = __ldg(reinterpret_cast<const float2*>(db2) + pr);
                float2 o2;
                o2.x = acc0 + b2.x;
                o2.y = acc1 + b2.y;
                *(reinterpret_cast<float2*>(out) + pr) = o2;
            }
        }
    }
}

// ---------------------------------------------------------------------------
// Inputs: x, t, TwE, PE, CE, mE, ext_W1, ext_b1, ext_W2, ext_b2,
//         dec_W1, dec_b1, dec_W2, dec_b2
// ---------------------------------------------------------------------------
extern "C" void kernel_launch(void* const* d_in, const int* in_sizes, int n_in,
                              void* d_out, int out_size)
{
    const float* x   = (const float*)d_in[0];
    const float* TwE = (const float*)d_in[2];
    const float* PE  = (const float*)d_in[3];
    const float* CE  = (const float*)d_in[4];
    const float* mE  = (const float*)d_in[5];
    const float* eW1 = (const float*)d_in[6];
    const float* eb1 = (const float*)d_in[7];
    const float* eW2 = (const float*)d_in[8];
    const float* eb2 = (const float*)d_in[9];
    const float* dW1 = (const float*)d_in[10];
    const float* db1 = (const float*)d_in[11];
    const float* dW2 = (const float*)d_in[12];
    const float* db2 = (const float*)d_in[13];
    float* out = (float*)d_out;

    const int xoff = in_sizes[0] - 4 * 256 * 128;

    fused_kernel<<<NBLK, NTHR>>>(x, TwE, PE, CE, mE,
                                 eW1, eb1, eW2, eb2,
                                 dW1, db1, dW2, db2,
                                 out, xoff);
    (void)n_in; (void)out_size;
}

// round 8
// speedup vs baseline: 10.0053x; 1.0132x over previous
#include <cuda_runtime.h>
#include <cstddef>

#define NBLK   148
#define NTHR   1024
#define NWARPS (NBLK * 32)       // 4736
#define NPAIRS 65536             // 131072 rows / 2
#define MDIM   450

// L2-resident split of dec_W2 (pairs of rows; 3600B/pair)
#define PR_RES   26624           // 26624*3600 = 95,846,400 B kept evict-normal
#define PF_LINES 748800u         // = PR_RES*3600/128 : exact resident line count
#define PF_PER_PHASE 187200u     // PF_LINES / 4 phases

// Scratch (device globals; no allocation)
__device__ __align__(16) float g_Fpart[128 * 128];
__device__ __align__(16) float g_feat[452];
__device__ __align__(16) float g_h[452];
__device__ __align__(16) float g_feat2[452];
__device__ __align__(16) float g_h2[452];

// Grid barrier (monotonic generation -> graph-replay safe)
__device__ unsigned g_count = 0;
__device__ volatile unsigned g_gen = 0;

__device__ __forceinline__ void grid_bar()
{
    __syncthreads();
    if (threadIdx.x == 0) {
        const unsigned gen = g_gen;
        __threadfence();
        if (atomicAdd(&g_count, 1u) == (unsigned)gridDim.x - 1u) {
            atomicExch(&g_count, 0u);
            __threadfence();
            g_gen = gen + 1u;
        } else {
            while (g_gen == gen) { }
            __threadfence();
        }
    }
    __syncthreads();
}

// Bounded L2 prefetch of the resident region only. phase in [0,4).
// Max touched byte = (PF_LINES-1)*128 + 127 < 95.9MB << 236MB allocation.
__device__ __forceinline__ void pf_resident(const float* dW2, int phase)
{
    const unsigned base = phase * PF_PER_PHASE;
    const unsigned hi   = base + PF_PER_PHASE;          // <= PF_LINES
    const unsigned my   = (blockIdx.x - 15) * NTHR + threadIdx.x; // 0..136191
    const char* p = (const char*)dW2;
    #pragma unroll
    for (unsigned k = 0; k < 2; ++k) {
        unsigned line = base + my + k * 136192u;
        if (line < hi)
            asm volatile("prefetch.global.L2 [%0];" :: "l"(p + (size_t)line * 128));
    }
}

// Warp-per-row 450x450 matvec: vout = [relu](W @ vin + b). Blocks 0..14.
__device__ __forceinline__ void mv450_stage(const float* __restrict__ W,
                                            const float* __restrict__ b,
                                            const float* __restrict__ vin_g,
                                            float* __restrict__ vout_g,
                                            bool do_relu, float* sh)
{
    const int tid = threadIdx.x;
    if (tid < MDIM) sh[tid] = __ldcg(vin_g + tid);
    __syncthreads();

    const int wid  = tid >> 5;
    const int lane = tid & 31;
    const int row  = blockIdx.x * 32 + wid;
    if (row < MDIM) {
        const float2* wr = reinterpret_cast<const float2*>(W + (size_t)row * MDIM);
        const float2* sv = reinterpret_cast<const float2*>(sh);
        float acc = 0.f;
        #pragma unroll
        for (int j = 0; j < 7; ++j) {
            const float2 w = __ldg(wr + lane + 32 * j);
            const float2 v = sv[lane + 32 * j];
            acc += w.x * v.x + w.y * v.y;
        }
        if (lane == 0) {
            const float2 w = __ldg(wr + 224);
            const float2 v = sv[224];
            acc += w.x * v.x + w.y * v.y;
        }
        #pragma unroll
        for (int o = 16; o; o >>= 1) acc += __shfl_xor_sync(0xFFFFFFFFu, acc, o);
        if (lane == 0) {
            float r = acc + __ldg(b + row);
            vout_g[row] = do_relu ? fmaxf(r, 0.f) : r;
        }
    }
}

// One dec row-pair dot: 3600B contiguous segment, 225 float4.
// STREAM=false -> __ldg (evict-normal, stays in L2); true -> __ldcs.
template<bool STREAM>
__device__ __forceinline__ void dec_pair(const float4* __restrict__ wr,
                                         const float4* __restrict__ VV,
                                         int lane, float& acc0, float& acc1)
{
    float4 w0 = STREAM ? __ldcs(wr + lane)       : __ldg(wr + lane);
    float4 w1 = STREAM ? __ldcs(wr + lane + 32)  : __ldg(wr + lane + 32);
    float4 w2 = STREAM ? __ldcs(wr + lane + 64)  : __ldg(wr + lane + 64);
    float4 w3 = STREAM ? __ldcs(wr + lane + 96)  : __ldg(wr + lane + 96);
    float4 w4 = STREAM ? __ldcs(wr + lane + 128) : __ldg(wr + lane + 128);
    float4 w5 = STREAM ? __ldcs(wr + lane + 160) : __ldg(wr + lane + 160);
    float4 w6 = STREAM ? __ldcs(wr + lane + 192) : __ldg(wr + lane + 192);
    float4 wt;
    if (lane == 0) wt = STREAM ? __ldcs(wr + 224) : __ldg(wr + 224);

    acc0 = 0.f; acc1 = 0.f;
    float4 v = VV[lane];
    acc0 += w0.x*v.x + w0.y*v.y + w0.z*v.z + w0.w*v.w;
    v = VV[lane + 32];
    acc0 += w1.x*v.x + w1.y*v.y + w1.z*v.z + w1.w*v.w;
    v = VV[lane + 64];
    acc0 += w2.x*v.x + w2.y*v.y + w2.z*v.z + w2.w*v.w;
    // straddle: float4 idx lane+96 covers elements 448..451 at lane 16
    v = VV[lane + 96];
    {
        float dlo = w3.x*v.x + w3.y*v.y;
        float dhi = w3.z*v.z + w3.w*v.w;
        acc0 += (lane < 16) ? (dlo + dhi) : ((lane == 16) ? dlo : 0.f);
        acc1 += (lane > 16) ? (dlo + dhi) : ((lane == 16) ? dhi : 0.f);
    }
    v = VV[lane + 128];
    acc1 += w4.x*v.x + w4.y*v.y + w4.z*v.z + w4.w*v.w;
    v = VV[lane + 160];
    acc1 += w5.x*v.x + w5.y*v.y + w5.z*v.z + w5.w*v.w;
    v = VV[lane + 192];
    acc1 += w6.x*v.x + w6.y*v.y + w6.z*v.z + w6.w*v.w;
    if (lane == 0) {
        v = VV[224];
        acc1 += wt.x*v.x + wt.y*v.y + wt.z*v.z + wt.w*v.w;
    }
}

__global__ void __launch_bounds__(NTHR, 1)
fused_kernel(const float* __restrict__ x,   const float* __restrict__ TwE,
             const float* __restrict__ PE,  const float* __restrict__ CE,
             const float* __restrict__ mE,
             const float* __restrict__ eW1, const float* __restrict__ eb1,
             const float* __restrict__ eW2, const float* __restrict__ eb2,
             const float* __restrict__ dW1, const float* __restrict__ db1,
             const float* __restrict__ dW2, const float* __restrict__ db2,
             float* __restrict__ out, int xoff)
{
    __shared__ float sh[10240];            // 40KB, reused per stage
    const int tid  = threadIdx.x;
    const int wid  = tid >> 5;
    const int lane = tid & 31;
    const int blk  = blockIdx.x;

    // ===== Stage 1: f partials. 128 blocks x 8 tp-rows each. =====
    if (blk < 128) {
        float* sx = sh;                    // [8][128] x rows
        float* sp = sh + 1024;             // [8 chunks][8 rows][128 i]
        sx[tid] = x[xoff + blk * 1024 + tid];
        __syncthreads();

        const int pr = wid & 3;
        const int ch = wid >> 2;
        const int i0 = lane * 4;
        const int r0 = pr * 2, r1 = r0 + 1;
        float4 a0 = {0,0,0,0}, a1 = {0,0,0,0};
        const int cb = ch * 16;
        #pragma unroll
        for (int cc = 0; cc < 16; ++cc) {
            const int c = cb + cc;
            const float4 ce = *reinterpret_cast<const float4*>(CE + c * 128 + i0);
            const float x0 = sx[r0 * 128 + c];
            const float x1 = sx[r1 * 128 + c];
            a0.x += x0 * ce.x; a0.y += x0 * ce.y; a0.z += x0 * ce.z; a0.w += x0 * ce.w;
            a1.x += x1 * ce.x; a1.y += x1 * ce.y; a1.z += x1 * ce.z; a1.w += x1 * ce.w;
        }
        *reinterpret_cast<float4*>(sp + (ch * 8 + r0) * 128 + i0) = a0;
        *reinterpret_cast<float4*>(sp + (ch * 8 + r1) * 128 + i0) = a1;
        __syncthreads();

        const int row = tid >> 7;
        const int i   = tid & 127;
        float s = 0.f;
        #pragma unroll
        for (int c2 = 0; c2 < 8; ++c2) s += sp[(c2 * 8 + row) * 128 + i];
        const int gr = blk * 8 + row;
        const int t  = gr >> 8;
        const int p  = gr & 255;
        s *= __ldg(PE + p * 128 + i) * __ldg(TwE + t * 128 + i);
        __syncthreads();
        sh[tid] = s;
        __syncthreads();
        if (tid < 128) {
            float t2 = 0.f;
            #pragma unroll
            for (int r = 0; r < 8; ++r) t2 += sh[r * 128 + tid];
            g_Fpart[blk * 128 + tid] = t2;
        }
    }
    grid_bar();

    // ===== Stage 2: feat = mE @ f (blocks 0..14); others prefetch phase 0 =====
    if (blk < 15) {
        // parallel reduce of 128 partials: 8 groups x 16
        float* tmp = sh + 1024;
        {
            const int grp = tid >> 7;      // 0..7
            const int i   = tid & 127;
            float s = 0.f;
            #pragma unroll
            for (int b = 0; b < 16; ++b)
                s += __ldcg(&g_Fpart[(grp * 16 + b) * 128 + i]);
            tmp[grp * 128 + i] = s;
        }
        __syncthreads();
        if (tid < 128) {
            float s = 0.f;
            #pragma unroll
            for (int g = 0; g < 8; ++g) s += tmp[g * 128 + tid];
            sh[tid] = s;
        }
        __syncthreads();
        const int row = blk * 32 + wid;
        if (row < MDIM) {
            const float* r = mE + row * 128;
            float acc = __ldg(r + lane)       * sh[lane]
                      + __ldg(r + lane + 32)  * sh[lane + 32]
                      + __ldg(r + lane + 64)  * sh[lane + 64]
                      + __ldg(r + lane + 96)  * sh[lane + 96];
            #pragma unroll
            for (int o = 16; o; o >>= 1) acc += __shfl_xor_sync(0xFFFFFFFFu, acc, o);
            if (lane == 0) g_feat[row] = acc;
        }
    } else {
        pf_resident(dW2, 0);
    }
    grid_bar();

    // ===== Stages 3..5: 450x450 chain (blocks 0..14); others prefetch =====
    if (blk < 15) mv450_stage(eW1, eb1, g_feat, g_h, true, sh);
    else pf_resident(dW2, 1);
    grid_bar();
    if (blk < 15) mv450_stage(eW2, eb2, g_h, g_feat2, false, sh);
    else pf_resident(dW2, 2);
    grid_bar();
    if (blk < 15) mv450_stage(dW1, db1, g_feat2, g_h2, true, sh);
    else pf_resident(dW2, 3);
    grid_bar();

    // ===== Stage 6: out = dec_W2 @ h2 + db2 (131072 x 450) =====
    {
        for (int i = tid; i < 900; i += NTHR)
            sh[i] = __ldcg(&g_h2[(i < 450) ? i : (i - 450)]);
        __syncthreads();
        const float4* VV = reinterpret_cast<const float4*>(sh);
        const int gw = blk * 32 + wid;

        int pr = gw;
        // resident half: evict-normal loads -> stays in L2 across graph replays
        for (; pr < PR_RES; pr += NWARPS) {
            const float4* wr = reinterpret_cast<const float4*>(dW2 + (size_t)pr * 900);
            float acc0, acc1;
            dec_pair<false>(wr, VV, lane, acc0, acc1);
            #pragma unroll
            for (int o = 16; o; o >>= 1) {
                acc0 += __shfl_xor_sync(0xFFFFFFFFu, acc0, o);
                acc1 += __shfl_xor_sync(0xFFFFFFFFu, acc1, o);
            }
            if (lane == 0) {
                const float2 b2 = __ldg(reinterpret_cast<const float2*>(db2) + pr);
                float2 o2; o2.x = acc0 + b2.x; o2.y = acc1 + b2.y;
                *(reinterpret_cast<float2*>(out) + pr) = o2;
            }
        }
        // streaming half: evict-first, doesn't displace the resident half
        for (; pr < NPAIRS; pr += NWARPS) {
            const float4* wr = reinterpret_cast<const float4*>(dW2 + (size_t)pr * 900);
            float acc0, acc1;
            dec_pair<true>(wr, VV, lane, acc0, acc1);
            #pragma unroll
            for (int o = 16; o; o >>= 1) {
                acc0 += __shfl_xor_sync(0xFFFFFFFFu, acc0, o);
                acc1 += __shfl_xor_sync(0xFFFFFFFFu, acc1, o);
            }
            if (lane == 0) {
                const float2 b2 = __ldg(reinterpret_cast<const float2*>(db2) + pr);
                float2 o2; o2.x = acc0 + b2.x; o2.y = acc1 + b2.y;
                *(reinterpret_cast<float2*>(out) + pr) = o2;
            }
        }
    }
}

// ---------------------------------------------------------------------------
// Inputs: x, t, TwE, PE, CE, mE, ext_W1, ext_b1, ext_W2, ext_b2,
//         dec_W1, dec_b1, dec_W2, dec_b2
// ---------------------------------------------------------------------------
extern "C" void kernel_launch(void* const* d_in, const int* in_sizes, int n_in,
                              void* d_out, int out_size)
{
    const float* x   = (const float*)d_in[0];
    const float* TwE = (const float*)d_in[2];
    const float* PE  = (const float*)d_in[3];
    const float* CE  = (const float*)d_in[4];
    const float* mE  = (const float*)d_in[5];
    const float* eW1 = (const float*)d_in[6];
    const float* eb1 = (const float*)d_in[7];
    const float* eW2 = (const float*)d_in[8];
    const float* eb2 = (const float*)d_in[9];
    const float* dW1 = (const float*)d_in[10];
    const float* db1 = (const float*)d_in[11];
    const float* dW2 = (const float*)d_in[12];
    const float* db2 = (const float*)d_in[13];
    float* out = (float*)d_out;

    const int xoff = in_sizes[0] - 4 * 256 * 128;

    fused_kernel<<<NBLK, NTHR>>>(x, TwE, PE, CE, mE,
                                 eW1, eb1, eW2, eb2,
                                 dW1, db1, dW2, db2,
                                 out, xoff);
    (void)n_in; (void)out_size;
}